// round 1
// baseline (speedup 1.0000x reference)
#include <cuda_runtime.h>
#include <cuda_bf16.h>
#include <math.h>

// Problem constants
#define S_LEN 2048
#define HID   2048
#define NH    16
#define DH    256
#define RR    64
#define NOPE  192
#define QL    1024
#define ORANK 512
#define NG    4
#define HD    (NH*DH)    // 4096
#define GO    (NG*ORANK) // 2048
#define EPSF  1e-6f
#define SCALE_F 0.0625f  // 256^-0.5

// ---------------- scratch (static device globals; no allocation) ----------------
__device__ float g_qlat[S_LEN * QL];    // 8 MB
__device__ float g_q   [S_LEN * HD];    // 32 MB
__device__ float g_kv  [S_LEN * DH];    // 2 MB
__device__ float g_o   [S_LEN * HD];    // 32 MB
__device__ float g_or  [S_LEN * GO];    // 16 MB

// ---------------- block reduction (256 threads) ----------------
__device__ __forceinline__ float blk_sum_256(float v) {
    __shared__ float red[8];
    #pragma unroll
    for (int o = 16; o; o >>= 1) v += __shfl_xor_sync(0xffffffffu, v, o);
    if ((threadIdx.x & 31) == 0) red[threadIdx.x >> 5] = v;
    __syncthreads();
    float t = 0.f;
    #pragma unroll
    for (int i = 0; i < 8; i++) t += red[i];
    return t;
}

// ---------------- generic GEMM: C[M,N] = A[M,K] * B[N,K]^T ----------------
// A row offset (n0/grpN)*grpStride supports the block-diagonal wo_a GEMM.
#define BM 128
#define BN 64
#define BK 16
__global__ void __launch_bounds__(256) gemm_bt_kernel(
    const float* __restrict__ A, const float* __restrict__ B, float* __restrict__ C,
    int M, int N, int K, int lda, int ldb, int ldc, int grpN, int grpStride)
{
    __shared__ __align__(16) float As[BK][BM + 4];
    __shared__ __align__(16) float Bs[BK][BN + 4];

    const int m0 = blockIdx.y * BM;
    const int n0 = blockIdx.x * BN;
    const float* Ap = A + (size_t)(n0 / grpN) * grpStride;
    const int tid = threadIdx.x;
    const int ty = tid >> 4, tx = tid & 15;

    float acc[8][4];
    #pragma unroll
    for (int i = 0; i < 8; i++)
        #pragma unroll
        for (int j = 0; j < 4; j++) acc[i][j] = 0.f;

    for (int k0 = 0; k0 < K; k0 += BK) {
        // stage A tile (transposed): 2 float4 per thread
        #pragma unroll
        for (int l = 0; l < 2; l++) {
            int lin = tid + l * 256;
            int row = lin >> 2;
            int kq  = (lin & 3) << 2;
            float4 v = *(const float4*)(Ap + (size_t)(m0 + row) * lda + k0 + kq);
            As[kq + 0][row] = v.x; As[kq + 1][row] = v.y;
            As[kq + 2][row] = v.z; As[kq + 3][row] = v.w;
        }
        // stage B tile (transposed): 1 float4 per thread
        {
            int row = tid >> 2;
            int kq  = (tid & 3) << 2;
            float4 v = *(const float4*)(B + (size_t)(n0 + row) * ldb + k0 + kq);
            Bs[kq + 0][row] = v.x; Bs[kq + 1][row] = v.y;
            Bs[kq + 2][row] = v.z; Bs[kq + 3][row] = v.w;
        }
        __syncthreads();
        #pragma unroll
        for (int kk = 0; kk < BK; kk++) {
            float a[8], b[4];
            *(float4*)(a + 0) = *(const float4*)(&As[kk][ty * 8]);
            *(float4*)(a + 4) = *(const float4*)(&As[kk][ty * 8 + 4]);
            *(float4*)(b)     = *(const float4*)(&Bs[kk][tx * 4]);
            #pragma unroll
            for (int i = 0; i < 8; i++)
                #pragma unroll
                for (int j = 0; j < 4; j++)
                    acc[i][j] = fmaf(a[i], b[j], acc[i][j]);
        }
        __syncthreads();
    }
    #pragma unroll
    for (int i = 0; i < 8; i++) {
        float4 v = make_float4(acc[i][0], acc[i][1], acc[i][2], acc[i][3]);
        *(float4*)(C + (size_t)(m0 + ty * 8 + i) * ldc + n0 + tx * 4) = v;
    }
}

// ---------------- q-latent RMS norm (row=1024, with weight) ----------------
__global__ void __launch_bounds__(256) qlat_norm_kernel(float* __restrict__ q,
                                                        const float* __restrict__ w)
{
    const int row = blockIdx.x;
    float* p = q + (size_t)row * QL;
    float4 v = *(float4*)(p + threadIdx.x * 4);
    float ssq = v.x * v.x + v.y * v.y + v.z * v.z + v.w * v.w;
    float tot = blk_sum_256(ssq);
    float inv = rsqrtf(tot * (1.f / QL) + EPSF);
    float4 wv = *(const float4*)(w + threadIdx.x * 4);
    v.x *= inv * wv.x; v.y *= inv * wv.y; v.z *= inv * wv.z; v.w *= inv * wv.w;
    *(float4*)(p + threadIdx.x * 4) = v;
}

// ---------------- per-head q norm + forward RoPE on last 64 dims ----------------
__global__ void __launch_bounds__(256) q_post_kernel(float* __restrict__ q,
                                                     const float* __restrict__ freqs)
{
    const int h = blockIdx.x, s = blockIdx.y, d = threadIdx.x;
    float* qp = q + (size_t)s * HD + h * DH;
    float v = qp[d];
    float tot = blk_sum_256(v * v);
    float nv = v * rsqrtf(tot * (1.f / DH) + EPSF);
    __shared__ float sh[DH];
    sh[d] = nv;
    __syncthreads();
    float outv = nv;
    if (d >= NOPE) {
        int p = (d - NOPE) >> 1;
        float f = freqs[s * (RR / 2) + p];
        float c = cosf(f), sn = sinf(f);
        outv = ((d & 1) == 0) ? sh[d] * c - sh[d + 1] * sn
                              : sh[d - 1] * sn + sh[d] * c;
    }
    qp[d] = outv;
}

// ---------------- kv RMS norm (weighted) + forward RoPE on last 64 dims ----------------
__global__ void __launch_bounds__(256) kv_post_kernel(float* __restrict__ kv,
                                                      const float* __restrict__ w,
                                                      const float* __restrict__ freqs)
{
    const int s = blockIdx.x, d = threadIdx.x;
    float* kp = kv + (size_t)s * DH;
    float v = kp[d];
    float tot = blk_sum_256(v * v);
    float nv = v * rsqrtf(tot * (1.f / DH) + EPSF) * w[d];
    __shared__ float sh[DH];
    sh[d] = nv;
    __syncthreads();
    float outv = nv;
    if (d >= NOPE) {
        int p = (d - NOPE) >> 1;
        float f = freqs[s * (RR / 2) + p];
        float c = cosf(f), sn = sinf(f);
        outv = ((d & 1) == 0) ? sh[d] * c - sh[d + 1] * sn
                              : sh[d - 1] * sn + sh[d] * c;
    }
    kp[d] = outv;
}

// ---------------- flash attention with sink + fused conj-RoPE epilogue ----------------
#define DP 260   // padded Q/K row (floats)
#define PSP 66   // padded P row
__global__ void __launch_bounds__(256) flash_kernel(
    const float* __restrict__ q, const float* __restrict__ kv,
    const float* __restrict__ freqs, const float* __restrict__ sink,
    float* __restrict__ o)
{
    extern __shared__ float sm[];
    float* Qs = sm;                 // 64 x DP
    float* Ks = sm + 64 * DP;       // 64 x DP (also serves as V)
    float* Ps = sm + 128 * DP;      // 64 x PSP

    const int h = blockIdx.y;
    const int q0 = (gridDim.x - 1 - blockIdx.x) * 64;  // heavy tiles first
    const int tid = threadIdx.x, ty = tid >> 4, tx = tid & 15;

    // load Q tile
    #pragma unroll
    for (int l = 0; l < 16; l++) {
        int lin = tid + l * 256;
        int r = lin >> 6, dq = (lin & 63) << 2;
        *(float4*)&Qs[r * DP + dq] =
            *(const float4*)(q + (size_t)(q0 + r) * HD + h * DH + dq);
    }

    float acc[4][16];
    #pragma unroll
    for (int i = 0; i < 4; i++)
        #pragma unroll
        for (int c = 0; c < 16; c++) acc[i][c] = 0.f;

    const float snk = sink[h];
    float m_i[4], l_i[4];
    #pragma unroll
    for (int i = 0; i < 4; i++) { m_i[i] = snk; l_i[i] = 1.f; }

    for (int t0 = 0; t0 <= q0; t0 += 64) {
        __syncthreads();  // Qs ready / previous PV finished with Ks
        #pragma unroll
        for (int l = 0; l < 16; l++) {
            int lin = tid + l * 256;
            int r = lin >> 6, dq = (lin & 63) << 2;
            *(float4*)&Ks[r * DP + dq] =
                *(const float4*)(kv + (size_t)(t0 + r) * DH + dq);
        }
        __syncthreads();

        // scores: 4x4 per thread over D=256
        float sc[4][4];
        #pragma unroll
        for (int i = 0; i < 4; i++)
            #pragma unroll
            for (int j = 0; j < 4; j++) sc[i][j] = 0.f;

        #pragma unroll 2
        for (int d4 = 0; d4 < DH; d4 += 4) {
            float4 qa[4], kb[4];
            #pragma unroll
            for (int i = 0; i < 4; i++) qa[i] = *(const float4*)&Qs[(ty * 4 + i) * DP + d4];
            #pragma unroll
            for (int j = 0; j < 4; j++) kb[j] = *(const float4*)&Ks[(tx * 4 + j) * DP + d4];
            #pragma unroll
            for (int i = 0; i < 4; i++)
                #pragma unroll
                for (int j = 0; j < 4; j++)
                    sc[i][j] += qa[i].x * kb[j].x + qa[i].y * kb[j].y
                              + qa[i].z * kb[j].z + qa[i].w * kb[j].w;
        }

        const bool diag = (t0 == q0);
        #pragma unroll
        for (int i = 0; i < 4; i++)
            #pragma unroll
            for (int j = 0; j < 4; j++) {
                sc[i][j] *= SCALE_F;
                if (diag && (tx * 4 + j) > (ty * 4 + i)) sc[i][j] = -1e30f;
            }

        // online softmax per row (16 lanes share a row group)
        #pragma unroll
        for (int i = 0; i < 4; i++) {
            float mt = fmaxf(fmaxf(sc[i][0], sc[i][1]), fmaxf(sc[i][2], sc[i][3]));
            #pragma unroll
            for (int off = 8; off; off >>= 1)
                mt = fmaxf(mt, __shfl_xor_sync(0xffffffffu, mt, off));
            float mnew = fmaxf(m_i[i], mt);
            float alpha = __expf(m_i[i] - mnew);
            float rs = 0.f;
            #pragma unroll
            for (int j = 0; j < 4; j++) {
                sc[i][j] = __expf(sc[i][j] - mnew);
                rs += sc[i][j];
            }
            #pragma unroll
            for (int off = 8; off; off >>= 1)
                rs += __shfl_xor_sync(0xffffffffu, rs, off);
            l_i[i] = l_i[i] * alpha + rs;
            m_i[i] = mnew;
            #pragma unroll
            for (int c = 0; c < 16; c++) acc[i][c] *= alpha;
            #pragma unroll
            for (int j = 0; j < 4; j++)
                Ps[(ty * 4 + i) * PSP + tx * 4 + j] = sc[i][j];
        }
        __syncthreads();

        // O += P @ V  (V == Ks)
        #pragma unroll 2
        for (int t = 0; t < 64; t++) {
            float p[4];
            #pragma unroll
            for (int i = 0; i < 4; i++) p[i] = Ps[(ty * 4 + i) * PSP + t];
            #pragma unroll
            for (int jc = 0; jc < 4; jc++) {
                float4 vv = *(const float4*)&Ks[t * DP + jc * 64 + tx * 4];
                #pragma unroll
                for (int i = 0; i < 4; i++) {
                    acc[i][jc * 4 + 0] = fmaf(p[i], vv.x, acc[i][jc * 4 + 0]);
                    acc[i][jc * 4 + 1] = fmaf(p[i], vv.y, acc[i][jc * 4 + 1]);
                    acc[i][jc * 4 + 2] = fmaf(p[i], vv.z, acc[i][jc * 4 + 2]);
                    acc[i][jc * 4 + 3] = fmaf(p[i], vv.w, acc[i][jc * 4 + 3]);
                }
            }
        }
    }

    // epilogue: normalize by l, conj-RoPE last 64 dims, store
    #pragma unroll
    for (int i = 0; i < 4; i++) {
        int r = q0 + ty * 4 + i;
        float invl = 1.f / l_i[i];
        float* orow = o + (size_t)r * HD + h * DH;
        #pragma unroll
        for (int jc = 0; jc < 3; jc++) {
            float4 v = make_float4(acc[i][jc * 4 + 0] * invl, acc[i][jc * 4 + 1] * invl,
                                   acc[i][jc * 4 + 2] * invl, acc[i][jc * 4 + 3] * invl);
            *(float4*)(orow + jc * 64 + tx * 4) = v;
        }
        {
            float v0 = acc[i][12] * invl, v1 = acc[i][13] * invl;
            float v2 = acc[i][14] * invl, v3 = acc[i][15] * invl;
            float f0 = freqs[r * (RR / 2) + tx * 2];
            float f1 = freqs[r * (RR / 2) + tx * 2 + 1];
            float c0 = cosf(f0), s0 = sinf(f0), c1 = cosf(f1), s1 = sinf(f1);
            float4 v = make_float4(v0 * c0 + v1 * s0, -v0 * s0 + v1 * c0,
                                   v2 * c1 + v3 * s1, -v2 * s1 + v3 * c1);
            *(float4*)(orow + NOPE + tx * 4) = v;
        }
    }
}

// ---------------- launch ----------------
extern "C" void kernel_launch(void* const* d_in, const int* in_sizes, int n_in,
                              void* d_out, int out_size)
{
    const float* x     = (const float*)d_in[0];
    const float* freqs = (const float*)d_in[1];
    const float* wq_a  = (const float*)d_in[2];
    const float* qnw   = (const float*)d_in[3];
    const float* wq_b  = (const float*)d_in[4];
    const float* wkv   = (const float*)d_in[5];
    const float* kvnw  = (const float*)d_in[6];
    const float* wo_a  = (const float*)d_in[7];
    const float* wo_b  = (const float*)d_in[8];
    const float* sink  = (const float*)d_in[9];
    float* out = (float*)d_out;
    (void)in_sizes; (void)n_in; (void)out_size;

    float *qlat, *qbuf, *kvbuf, *obuf, *orbuf;
    cudaGetSymbolAddress((void**)&qlat,  g_qlat);
    cudaGetSymbolAddress((void**)&qbuf,  g_q);
    cudaGetSymbolAddress((void**)&kvbuf, g_kv);
    cudaGetSymbolAddress((void**)&obuf,  g_o);
    cudaGetSymbolAddress((void**)&orbuf, g_or);

    const int BIGN = 1 << 30;

    // 1) q_lat = x @ wq_a^T ; RMS norm
    gemm_bt_kernel<<<dim3(QL / BN, S_LEN / BM), 256>>>(
        x, wq_a, qlat, S_LEN, QL, HID, HID, HID, QL, BIGN, 0);
    qlat_norm_kernel<<<S_LEN, 256>>>(qlat, qnw);

    // 2) q = q_lat @ wq_b^T ; per-head norm + RoPE
    gemm_bt_kernel<<<dim3(HD / BN, S_LEN / BM), 256>>>(
        qlat, wq_b, qbuf, S_LEN, HD, QL, QL, QL, HD, BIGN, 0);
    q_post_kernel<<<dim3(NH, S_LEN), 256>>>(qbuf, freqs);

    // 3) kv = rms(x @ wkv^T) ; RoPE
    gemm_bt_kernel<<<dim3(DH / BN, S_LEN / BM), 256>>>(
        x, wkv, kvbuf, S_LEN, DH, HID, HID, HID, DH, BIGN, 0);
    kv_post_kernel<<<S_LEN, 256>>>(kvbuf, kvnw, freqs);

    // 4) flash attention with sink + conj-RoPE epilogue
    size_t smem = (size_t)(2 * 64 * DP + 64 * PSP) * sizeof(float);
    cudaFuncSetAttribute(flash_kernel, cudaFuncAttributeMaxDynamicSharedMemorySize, (int)smem);
    flash_kernel<<<dim3(S_LEN / 64, NH), 256, smem>>>(qbuf, kvbuf, freqs, sink, obuf);

    // 5) grouped o_r GEMM (block-diagonal wo_a)
    gemm_bt_kernel<<<dim3(GO / BN, S_LEN / BM), 256>>>(
        obuf, wo_a, orbuf, S_LEN, GO, NG * DH, HD, NG * DH, GO, ORANK, NG * DH);

    // 6) out = o_r @ wo_b^T
    gemm_bt_kernel<<<dim3(HID / BN, S_LEN / BM), 256>>>(
        orbuf, wo_b, out, S_LEN, HID, GO, GO, GO, HID, BIGN, 0);
}